// round 1
// baseline (speedup 1.0000x reference)
#include <cuda_runtime.h>
#include <math.h>
#include <stdint.h>

#define N_TOK 16384
#define DIM   1024
#define NEXP  8
#define HID   2048
#define NK    (N_TOK * 2)   // 32768 (token, expert) assignments

// ---------------- scratch (device globals: no allocations allowed) -------------
__device__ int   g_top_idx[NK];            // per token: 2 expert ids
__device__ float g_top_w[NK];              // per token: 2 renormalized weights
__device__ int   g_off[NEXP + 1];          // expert segment offsets
__device__ int   g_cursor[NEXP];           // scatter cursors
__device__ int   g_tok[NK];                // slot -> token id
__device__ int   g_pos[NK];                // assignment (2n+k) -> slot
__device__ float g_h[(size_t)NK * HID];    // 256 MB: gelu(x @ W1 + b1)
__device__ float g_y[(size_t)NK * DIM];    // 128 MB: h @ W2 + b2

// ---------------- helpers ------------------------------------------------------
__device__ __forceinline__ float to_tf32(float x) {
    uint32_t u;
    asm("cvt.rna.tf32.f32 %0, %1;" : "=r"(u) : "f"(x));
    return __uint_as_float(u);
}

__device__ __forceinline__ void mma_tf32(float* c, const uint32_t* a, const uint32_t* b) {
    asm volatile(
        "mma.sync.aligned.m16n8k8.row.col.f32.tf32.tf32.f32 "
        "{%0,%1,%2,%3}, {%4,%5,%6,%7}, {%8,%9}, {%0,%1,%2,%3};\n"
        : "+f"(c[0]), "+f"(c[1]), "+f"(c[2]), "+f"(c[3])
        : "r"(a[0]), "r"(a[1]), "r"(a[2]), "r"(a[3]), "r"(b[0]), "r"(b[1]));
}

__device__ __forceinline__ float gelu_exact(float v) {
    return 0.5f * v * (1.0f + erff(v * 0.70710678118654752f));
}

// ---------------- 1) gating: logits, top-2, renormalized weights ---------------
__global__ void gate_kernel(const float* __restrict__ x,
                            const float* __restrict__ Wg,
                            const float* __restrict__ bg) {
    int warp = (blockIdx.x * blockDim.x + threadIdx.x) >> 5;
    int lane = threadIdx.x & 31;
    if (warp >= N_TOK) return;
    const float* xr = x + (size_t)warp * DIM;

    float acc[NEXP];
#pragma unroll
    for (int e = 0; e < NEXP; e++) acc[e] = 0.f;

    for (int j = 0; j < DIM / 32; j++) {
        int d = j * 32 + lane;
        float xv = xr[d];
        const float4* wr = (const float4*)(Wg + (size_t)d * NEXP);
        float4 w0 = wr[0], w1 = wr[1];
        acc[0] += xv * w0.x; acc[1] += xv * w0.y;
        acc[2] += xv * w0.z; acc[3] += xv * w0.w;
        acc[4] += xv * w1.x; acc[5] += xv * w1.y;
        acc[6] += xv * w1.z; acc[7] += xv * w1.w;
    }
#pragma unroll
    for (int e = 0; e < NEXP; e++) {
#pragma unroll
        for (int s = 16; s > 0; s >>= 1)
            acc[e] += __shfl_xor_sync(0xffffffffu, acc[e], s);
    }
    if (lane == 0) {
        float l[NEXP];
#pragma unroll
        for (int e = 0; e < NEXP; e++) l[e] = acc[e] + bg[e];
        int i0 = 0;
#pragma unroll
        for (int e = 1; e < NEXP; e++) if (l[e] > l[i0]) i0 = e;
        int i1 = (i0 == 0) ? 1 : 0;
#pragma unroll
        for (int e = 0; e < NEXP; e++) {
            if (e == i0) continue;
            if (l[e] > l[i1]) i1 = e;
        }
        // softmax + top-2 renorm == 2-way logistic on the two top logits
        float w0 = 1.f / (1.f + expf(l[i1] - l[i0]));
        g_top_idx[2 * warp]     = i0;
        g_top_idx[2 * warp + 1] = i1;
        g_top_w[2 * warp]       = w0;
        g_top_w[2 * warp + 1]   = 1.f - w0;
    }
}

// ---------------- 2) count per-expert + exclusive scan -------------------------
__global__ void count_kernel() {
    __shared__ int cnt[NEXP];
    int tid = threadIdx.x;
    if (tid < NEXP) cnt[tid] = 0;
    __syncthreads();
    for (int i = tid; i < NK; i += blockDim.x)
        atomicAdd(&cnt[g_top_idx[i]], 1);
    __syncthreads();
    if (tid == 0) {
        int run = 0;
        for (int e = 0; e < NEXP; e++) {
            g_off[e] = run; g_cursor[e] = run; run += cnt[e];
        }
        g_off[NEXP] = run;
    }
}

// ---------------- 3) scatter assignments into expert-contiguous slots ----------
__global__ void scatter_kernel() {
    int i = blockIdx.x * blockDim.x + threadIdx.x;
    if (i >= NK) return;
    int e = g_top_idx[i];
    int p = atomicAdd(&g_cursor[e], 1);
    g_tok[p] = i >> 1;
    g_pos[i] = p;
}

// ---------------- 4/5) expert-grouped tf32 GEMM --------------------------------
// Tile 128x128, BK=16, 8 warps as 4(m) x 2(n): warp tile 32x64, m16n8k8 tf32.
// GATHER: A rows come from x via g_tok (GEMM1). Else A = g_h rows (GEMM2).
// DOGELU: epilogue bias+gelu -> g_h (GEMM1). Else bias -> g_y (GEMM2).
template <int KDIM, int NCOLS, bool GATHER, bool DOGELU>
__global__ __launch_bounds__(256, 2)
void gemm_kernel(const float* __restrict__ Abase,
                 const float* __restrict__ Bbase,
                 const float* __restrict__ biasbase) {
    const int e     = blockIdx.z;
    const int moff  = g_off[e];
    const int M     = g_off[e + 1] - moff;
    const int rows0 = blockIdx.x * 128;
    if (rows0 >= M) return;
    const int n0 = blockIdx.y * 128;

    const float* Aptr = GATHER ? Abase : (const float*)g_h;
    const float* B    = Bbase + (size_t)e * KDIM * NCOLS;
    const float* bias = biasbase + (size_t)e * NCOLS;
    float*       Cptr = DOGELU ? g_h : g_y;

    __shared__ float As[128 * 20];   // pad 20: conflict-free fragment reads
    __shared__ float Bs[16 * 136];   // pad 136: conflict-free fragment reads
    __shared__ int   sSrc[128];      // source row per tile row (-1 = OOB)

    const int tid = threadIdx.x;
    if (tid < 128) {
        int s = rows0 + tid;
        if (s < M) sSrc[tid] = GATHER ? g_tok[moff + s] : (moff + s);
        else       sSrc[tid] = -1;
    }

    const int warp = tid >> 5, lane = tid & 31;
    const int wm = warp >> 1, wn = warp & 1;     // 4 x 2 warp grid
    const int g = lane >> 2,  t = lane & 3;

    float acc[2][8][4];
#pragma unroll
    for (int mi = 0; mi < 2; mi++)
#pragma unroll
        for (int ni = 0; ni < 8; ni++)
#pragma unroll
            for (int q = 0; q < 4; q++) acc[mi][ni][q] = 0.f;

    for (int k0 = 0; k0 < KDIM; k0 += 16) {
        __syncthreads();
        // A tile: 128 rows x 16 cols (2 float4 per thread), tf32-rounded at store
#pragma unroll
        for (int it = 0; it < 2; it++) {
            int idx = tid + it * 256;
            int r = idx >> 2, c = (idx & 3) * 4;
            int src = sSrc[r];
            float4 v = make_float4(0.f, 0.f, 0.f, 0.f);
            if (src >= 0) v = *(const float4*)(Aptr + (size_t)src * KDIM + k0 + c);
            v.x = to_tf32(v.x); v.y = to_tf32(v.y);
            v.z = to_tf32(v.z); v.w = to_tf32(v.w);
            *(float4*)&As[r * 20 + c] = v;
        }
        // B tile: 16 rows x 128 cols
#pragma unroll
        for (int it = 0; it < 2; it++) {
            int idx = tid + it * 256;
            int r = idx >> 5, c = (idx & 31) * 4;
            float4 v = *(const float4*)(B + (size_t)(k0 + r) * NCOLS + n0 + c);
            v.x = to_tf32(v.x); v.y = to_tf32(v.y);
            v.z = to_tf32(v.z); v.w = to_tf32(v.w);
            *(float4*)&Bs[r * 136 + c] = v;
        }
        __syncthreads();

#pragma unroll
        for (int kk = 0; kk < 16; kk += 8) {
            uint32_t af[2][4], bf[8][2];
#pragma unroll
            for (int mi = 0; mi < 2; mi++) {
                int r0 = wm * 32 + mi * 16 + g;
                af[mi][0] = __float_as_uint(As[r0 * 20 + kk + t]);
                af[mi][1] = __float_as_uint(As[(r0 + 8) * 20 + kk + t]);
                af[mi][2] = __float_as_uint(As[r0 * 20 + kk + t + 4]);
                af[mi][3] = __float_as_uint(As[(r0 + 8) * 20 + kk + t + 4]);
            }
#pragma unroll
            for (int ni = 0; ni < 8; ni++) {
                int col = wn * 64 + ni * 8 + g;
                bf[ni][0] = __float_as_uint(Bs[(kk + t) * 136 + col]);
                bf[ni][1] = __float_as_uint(Bs[(kk + t + 4) * 136 + col]);
            }
#pragma unroll
            for (int mi = 0; mi < 2; mi++)
#pragma unroll
                for (int ni = 0; ni < 8; ni++)
                    mma_tf32(acc[mi][ni], af[mi], bf[ni]);
        }
    }

    // epilogue
#pragma unroll
    for (int ni = 0; ni < 8; ni++) {
        int col = n0 + wn * 64 + ni * 8 + t * 2;
        float bv0 = bias[col], bv1 = bias[col + 1];
#pragma unroll
        for (int mi = 0; mi < 2; mi++) {
#pragma unroll
            for (int half = 0; half < 2; half++) {
                int r = rows0 + wm * 32 + mi * 16 + g + half * 8;
                if (r < M) {
                    float v0 = acc[mi][ni][half * 2 + 0] + bv0;
                    float v1 = acc[mi][ni][half * 2 + 1] + bv1;
                    if (DOGELU) { v0 = gelu_exact(v0); v1 = gelu_exact(v1); }
                    *(float2*)&Cptr[(size_t)(moff + r) * NCOLS + col] = make_float2(v0, v1);
                }
            }
        }
    }
}

// ---------------- 6) combine: residual + weighted expert outputs ---------------
__global__ void combine_kernel(const float* __restrict__ x, float* __restrict__ out) {
    int idx = blockIdx.x * blockDim.x + threadIdx.x;   // over N * (D/4)
    int n = idx >> 8;            // D/4 = 256
    int c = (idx & 255) * 4;
    int p0 = g_pos[2 * n], p1 = g_pos[2 * n + 1];
    float w0 = g_top_w[2 * n], w1 = g_top_w[2 * n + 1];
    float4 xv = *(const float4*)(x + (size_t)n * DIM + c);
    float4 y0 = *(const float4*)(g_y + (size_t)p0 * DIM + c);
    float4 y1 = *(const float4*)(g_y + (size_t)p1 * DIM + c);
    float4 o;
    o.x = xv.x + w0 * y0.x + w1 * y1.x;
    o.y = xv.y + w0 * y0.y + w1 * y1.y;
    o.z = xv.z + w0 * y0.z + w1 * y1.z;
    o.w = xv.w + w0 * y0.w + w1 * y1.w;
    *(float4*)(out + (size_t)n * DIM + c) = o;
}

// ---------------- launch -------------------------------------------------------
extern "C" void kernel_launch(void* const* d_in, const int* in_sizes, int n_in,
                              void* d_out, int out_size) {
    const float* x  = (const float*)d_in[0];
    const float* Wg = (const float*)d_in[1];
    const float* bg = (const float*)d_in[2];
    const float* W1 = (const float*)d_in[3];
    const float* b1 = (const float*)d_in[4];
    const float* W2 = (const float*)d_in[5];
    const float* b2 = (const float*)d_in[6];
    float* out = (float*)d_out;

    gate_kernel<<<N_TOK / 8, 256>>>(x, Wg, bg);
    count_kernel<<<1, 256>>>();
    scatter_kernel<<<NK / 256, 256>>>();
    // GEMM1: h = gelu(x_gathered @ W1[e] + b1[e])   [32768, 2048]
    gemm_kernel<DIM, HID, true, true>
        <<<dim3(N_TOK / 128, HID / 128, NEXP), 256>>>(x, W1, b1);
    // GEMM2: y = h @ W2[e] + b2[e]                  [32768, 1024]
    gemm_kernel<HID, DIM, false, false>
        <<<dim3(N_TOK / 128, DIM / 128, NEXP), 256>>>(x, W2, b2);
    // out = x + w0*y[p0] + w1*y[p1]
    combine_kernel<<<N_TOK, 256>>>(x, out);
}

// round 3
// speedup vs baseline: 3.0965x; 3.0965x over previous
#include <cuda_runtime.h>
#include <cuda_fp16.h>
#include <math.h>
#include <stdint.h>

#define N_TOK 16384
#define DIM   1024
#define NEXP  8
#define HID   2048
#define NK    (N_TOK * 2)

// ---------------- scratch (no allocations allowed) -----------------------------
__device__ int    g_top_idx[NK];
__device__ float  g_top_w[NK];
__device__ int    g_off[NEXP + 1];
__device__ int    g_cursor[NEXP];
__device__ int    g_tok[NK];
__device__ int    g_pos[NK];
__device__ __half g_xh[(size_t)N_TOK * DIM];      // 32 MB  x in fp16
__device__ __half g_w1h[(size_t)NEXP * DIM * HID]; // 32 MB  W1 fp16
__device__ __half g_w2h[(size_t)NEXP * HID * DIM]; // 32 MB  W2 fp16
__device__ __half g_h[(size_t)NK * HID];          // 134 MB gelu(xW1+b1) fp16
__device__ float  g_y[(size_t)NK * DIM];          // 134 MB hW2+b2 fp32

// ---------------- PTX helpers --------------------------------------------------
__device__ __forceinline__ uint32_t smem_u32(const void* p) {
    uint32_t a;
    asm("{ .reg .u64 t; cvta.to.shared.u64 t, %1; cvt.u32.u64 %0, t; }" : "=r"(a) : "l"(p));
    return a;
}
__device__ __forceinline__ void cp16(uint32_t d, const void* s) {
    asm volatile("cp.async.cg.shared.global [%0], [%1], 16;" :: "r"(d), "l"(s));
}
#define CP_COMMIT() asm volatile("cp.async.commit_group;" ::: "memory")
#define CP_WAIT2()  asm volatile("cp.async.wait_group 2;" ::: "memory")

__device__ __forceinline__ void ldsm4(uint32_t* r, uint32_t a) {
    asm volatile("ldmatrix.sync.aligned.m8n8.x4.shared.b16 {%0,%1,%2,%3}, [%4];"
                 : "=r"(r[0]), "=r"(r[1]), "=r"(r[2]), "=r"(r[3]) : "r"(a));
}
__device__ __forceinline__ void ldsm4t(uint32_t* r, uint32_t a) {
    asm volatile("ldmatrix.sync.aligned.m8n8.x4.trans.shared.b16 {%0,%1,%2,%3}, [%4];"
                 : "=r"(r[0]), "=r"(r[1]), "=r"(r[2]), "=r"(r[3]) : "r"(a));
}
__device__ __forceinline__ void mma16816(float* c, const uint32_t* a, const uint32_t* b) {
    asm volatile("mma.sync.aligned.m16n8k16.row.col.f32.f16.f16.f32 "
                 "{%0,%1,%2,%3}, {%4,%5,%6,%7}, {%8,%9}, {%0,%1,%2,%3};"
                 : "+f"(c[0]), "+f"(c[1]), "+f"(c[2]), "+f"(c[3])
                 : "r"(a[0]), "r"(a[1]), "r"(a[2]), "r"(a[3]), "r"(b[0]), "r"(b[1]));
}
__device__ __forceinline__ float gelu_exact(float v) {
    return 0.5f * v * (1.0f + erff(v * 0.70710678118654752f));
}

// ---------------- fp32 -> fp16 convert -----------------------------------------
__global__ void cvt_kernel(const float* __restrict__ s, __half* __restrict__ d, int n4) {
    int i = blockIdx.x * blockDim.x + threadIdx.x;
    int stride = gridDim.x * blockDim.x;
    for (; i < n4; i += stride) {
        float4 v = ((const float4*)s)[i];
        __half2 h0 = __floats2half2_rn(v.x, v.y);
        __half2 h1 = __floats2half2_rn(v.z, v.w);
        ((uint2*)d)[i] = make_uint2(*(uint32_t*)&h0, *(uint32_t*)&h1);
    }
}

// ---------------- gating -------------------------------------------------------
__global__ void gate_kernel(const float* __restrict__ x,
                            const float* __restrict__ Wg,
                            const float* __restrict__ bg) {
    int warp = (blockIdx.x * blockDim.x + threadIdx.x) >> 5;
    int lane = threadIdx.x & 31;
    if (warp >= N_TOK) return;
    const float* xr = x + (size_t)warp * DIM;
    float acc[NEXP];
#pragma unroll
    for (int e = 0; e < NEXP; e++) acc[e] = 0.f;
    for (int j = 0; j < DIM / 32; j++) {
        int d = j * 32 + lane;
        float xv = xr[d];
        const float4* wr = (const float4*)(Wg + (size_t)d * NEXP);
        float4 w0 = wr[0], w1 = wr[1];
        acc[0] += xv * w0.x; acc[1] += xv * w0.y;
        acc[2] += xv * w0.z; acc[3] += xv * w0.w;
        acc[4] += xv * w1.x; acc[5] += xv * w1.y;
        acc[6] += xv * w1.z; acc[7] += xv * w1.w;
    }
#pragma unroll
    for (int e = 0; e < NEXP; e++)
#pragma unroll
        for (int s = 16; s > 0; s >>= 1)
            acc[e] += __shfl_xor_sync(0xffffffffu, acc[e], s);
    if (lane == 0) {
        float l[NEXP];
#pragma unroll
        for (int e = 0; e < NEXP; e++) l[e] = acc[e] + bg[e];
        int i0 = 0;
#pragma unroll
        for (int e = 1; e < NEXP; e++) if (l[e] > l[i0]) i0 = e;
        int i1 = (i0 == 0) ? 1 : 0;
#pragma unroll
        for (int e = 0; e < NEXP; e++) {
            if (e == i0) continue;
            if (l[e] > l[i1]) i1 = e;
        }
        float w0 = 1.f / (1.f + expf(l[i1] - l[i0]));
        g_top_idx[2 * warp]     = i0;
        g_top_idx[2 * warp + 1] = i1;
        g_top_w[2 * warp]       = w0;
        g_top_w[2 * warp + 1]   = 1.f - w0;
    }
}

__global__ void count_kernel() {
    __shared__ int cnt[NEXP];
    int tid = threadIdx.x;
    if (tid < NEXP) cnt[tid] = 0;
    __syncthreads();
    for (int i = tid; i < NK; i += blockDim.x)
        atomicAdd(&cnt[g_top_idx[i]], 1);
    __syncthreads();
    if (tid == 0) {
        int run = 0;
        for (int e = 0; e < NEXP; e++) { g_off[e] = run; g_cursor[e] = run; run += cnt[e]; }
        g_off[NEXP] = run;
    }
}

__global__ void scatter_kernel() {
    int i = blockIdx.x * blockDim.x + threadIdx.x;
    if (i >= NK) return;
    int e = g_top_idx[i];
    int p = atomicAdd(&g_cursor[e], 1);
    g_tok[p] = i >> 1;
    g_pos[i] = p;
}

// ---------------- fp16 expert GEMM (mma.sync + ldmatrix + cp.async) ------------
// BM=128, BN=256, BK=32, 512 threads (16 warps 4x4, warp tile 32x64), 4 stages.
// A smem: 128 rows x 32 halfs, pitch 80B (5x16B units, 5r%8 bijective -> LDSM ok)
// B smem: 32 k-rows x 256 halfs, pitch 528B (33 units, 33k%8 bijective)
#define BM 128
#define BN 256
#define BK 32
#define NST 4
#define A_PITCH 80
#define B_PITCH 528
#define STG_A   (BM * A_PITCH)               // 10240
#define STG_B   (BK * B_PITCH)               // 16896
#define STG_SZ  (STG_A + STG_B)              // 27136
#define OFF_BIAS (STG_SZ * NST)              // 108544
#define OFF_SRC  (OFF_BIAS + BN * 4)         // 109568
#define SMEM_BYTES (OFF_SRC + BM * 4)        // 110080

template <int KDIM, int NCOLS, bool GATHER, bool DOGELU>
__global__ __launch_bounds__(512, 1) void hgemm(
    const __half* __restrict__ Abase, const __half* __restrict__ Bbase,
    const float* __restrict__ biasbase) {
    extern __shared__ __align__(128) char smem[];
    const int e     = blockIdx.z;
    const int moff  = g_off[e];
    const int M     = g_off[e + 1] - moff;
    const int rows0 = blockIdx.x * BM;
    if (rows0 >= M) return;
    const int n0 = blockIdx.y * BN;

    const __half* Bexp = Bbase + (size_t)e * KDIM * NCOLS;
    const uint32_t sb = smem_u32(smem);
    const int tid  = threadIdx.x;
    const int wid  = tid >> 5, lane = tid & 31;
    const int wm = wid >> 2, wn = wid & 3;     // 4x4 warps, warp 32(m) x 64(n)
    const int g = lane >> 2, t = lane & 3;

    int*   sSrc  = (int*)(smem + OFF_SRC);
    float* sBias = (float*)(smem + OFF_BIAS);
    if (tid < BM) {
        int s = rows0 + tid; if (s >= M) s = M - 1;
        sSrc[tid] = GATHER ? g_tok[moff + s] : (moff + s);
    }
    if (tid < BN / 4)
        ((float4*)sBias)[tid] = ((const float4*)(biasbase + (size_t)e * NCOLS + n0))[tid];
    __syncthreads();

    // per-thread fill constants
    const int r_a = tid >> 2, c_a = tid & 3;                       // A: 1 chunk
    const __half* aRow = Abase + (size_t)sSrc[r_a] * KDIM;
    const uint32_t aDst = (uint32_t)(r_a * A_PITCH + c_a * 16);
    const int kb0 = tid >> 5, nc0 = tid & 31;                      // B: 2 chunks
    const __half* bRow0 = Bexp + (size_t)kb0 * NCOLS + n0 + nc0 * 8;
    const __half* bRow1 = Bexp + (size_t)(kb0 + 16) * NCOLS + n0 + nc0 * 8;
    const uint32_t bDst0 = (uint32_t)(STG_A + kb0 * B_PITCH + nc0 * 16);
    const uint32_t bDst1 = bDst0 + 16 * B_PITCH;

    auto fill = [&](int kc) {
        int s = kc & (NST - 1);
        uint32_t base = sb + s * STG_SZ;
        cp16(base + aDst, aRow + kc * BK + c_a * 8);
        cp16(base + bDst0, bRow0 + (size_t)kc * BK * NCOLS);
        cp16(base + bDst1, bRow1 + (size_t)kc * BK * NCOLS);
    };

    // LDSM lane addresses (byte offsets within stage)
    const int lr = lane & 15, ls = lane >> 4;
    uint32_t aAddr[2], bAddr[2][4];
#pragma unroll
    for (int mi = 0; mi < 2; mi++)
        aAddr[mi] = (uint32_t)((wm * 32 + mi * 16 + lr) * A_PITCH + ls * 16);
#pragma unroll
    for (int kk = 0; kk < 2; kk++)
#pragma unroll
        for (int p = 0; p < 4; p++)
            bAddr[kk][p] = (uint32_t)(STG_A + (kk * 16 + lr) * B_PITCH +
                                      (wn * 8 + p * 2 + ls) * 16);

    float acc[2][8][4];
#pragma unroll
    for (int mi = 0; mi < 2; mi++)
#pragma unroll
        for (int ni = 0; ni < 8; ni++)
#pragma unroll
            for (int q = 0; q < 4; q++) acc[mi][ni][q] = 0.f;

    const int NC = KDIM / BK;
    fill(0); CP_COMMIT();
    fill(1); CP_COMMIT();
    fill(2); CP_COMMIT();

    for (int kc = 0; kc < NC; kc++) {
        int s = kc & (NST - 1);
        uint32_t base = sb + s * STG_SZ;
        CP_WAIT2();
        __syncthreads();
#pragma unroll
        for (int kk = 0; kk < 2; kk++) {
            uint32_t af[2][4], bf[8][2];
#pragma unroll
            for (int mi = 0; mi < 2; mi++)
                ldsm4(af[mi], base + aAddr[mi] + kk * 32);
#pragma unroll
            for (int p = 0; p < 4; p++) {
                uint32_t r4[4];
                ldsm4t(r4, base + bAddr[kk][p]);
                bf[2 * p][0] = r4[0]; bf[2 * p][1] = r4[1];
                bf[2 * p + 1][0] = r4[2]; bf[2 * p + 1][1] = r4[3];
            }
#pragma unroll
            for (int mi = 0; mi < 2; mi++)
#pragma unroll
                for (int ni = 0; ni < 8; ni++)
                    mma16816(acc[mi][ni], af[mi], bf[ni]);
        }
        if (kc + 3 < NC) fill(kc + 3);
        CP_COMMIT();
    }
    __syncthreads();

    if (DOGELU) {
        // bias + gelu -> half2, stage through smem, coalesced STG.128 to g_h
        char* ep = smem;
#pragma unroll
        for (int mi = 0; mi < 2; mi++)
#pragma unroll
            for (int ni = 0; ni < 8; ni++) {
                int col = wn * 64 + ni * 8 + 2 * t;
                float bv0 = sBias[col], bv1 = sBias[col + 1];
                int rlo = wm * 32 + mi * 16 + g;
                float v0 = gelu_exact(acc[mi][ni][0] + bv0);
                float v1 = gelu_exact(acc[mi][ni][1] + bv1);
                float v2 = gelu_exact(acc[mi][ni][2] + bv0);
                float v3 = gelu_exact(acc[mi][ni][3] + bv1);
                __half2 hlo = __floats2half2_rn(v0, v1);
                __half2 hhi = __floats2half2_rn(v2, v3);
                *(__half2*)(ep + rlo * B_PITCH + col * 2) = hlo;
                *(__half2*)(ep + (rlo + 8) * B_PITCH + col * 2) = hhi;
            }
        __syncthreads();
#pragma unroll
        for (int it = 0; it < 8; it++) {
            int id = it * 512 + tid;
            int r = id >> 5, c = id & 31;
            if (rows0 + r < M) {
                uint4 v = *(uint4*)(ep + r * B_PITCH + c * 16);
                *(uint4*)(g_h + (size_t)(moff + rows0 + r) * NCOLS + n0 + c * 8) = v;
            }
        }
    } else {
        // bias -> fp32, direct coalesced STG.64 pairs to g_y
#pragma unroll
        for (int mi = 0; mi < 2; mi++)
#pragma unroll
            for (int ni = 0; ni < 8; ni++) {
                int col = wn * 64 + ni * 8 + 2 * t;
                float bv0 = sBias[col], bv1 = sBias[col + 1];
                int rlo = rows0 + wm * 32 + mi * 16 + g;
                if (rlo < M)
                    *(float2*)(g_y + (size_t)(moff + rlo) * NCOLS + n0 + col) =
                        make_float2(acc[mi][ni][0] + bv0, acc[mi][ni][1] + bv1);
                if (rlo + 8 < M)
                    *(float2*)(g_y + (size_t)(moff + rlo + 8) * NCOLS + n0 + col) =
                        make_float2(acc[mi][ni][2] + bv0, acc[mi][ni][3] + bv1);
            }
    }
}

// ---------------- combine ------------------------------------------------------
__global__ void combine_kernel(const float* __restrict__ x, float* __restrict__ out) {
    int idx = blockIdx.x * blockDim.x + threadIdx.x;
    int n = idx >> 8;
    int c = (idx & 255) * 4;
    int p0 = g_pos[2 * n], p1 = g_pos[2 * n + 1];
    float w0 = g_top_w[2 * n], w1 = g_top_w[2 * n + 1];
    float4 xv = *(const float4*)(x + (size_t)n * DIM + c);
    float4 y0 = *(const float4*)(g_y + (size_t)p0 * DIM + c);
    float4 y1 = *(const float4*)(g_y + (size_t)p1 * DIM + c);
    float4 o;
    o.x = xv.x + w0 * y0.x + w1 * y1.x;
    o.y = xv.y + w0 * y0.y + w1 * y1.y;
    o.z = xv.z + w0 * y0.z + w1 * y1.z;
    o.w = xv.w + w0 * y0.w + w1 * y1.w;
    *(float4*)(out + (size_t)n * DIM + c) = o;
}

// ---------------- launch -------------------------------------------------------
extern "C" void kernel_launch(void* const* d_in, const int* in_sizes, int n_in,
                              void* d_out, int out_size) {
    const float* x  = (const float*)d_in[0];
    const float* Wg = (const float*)d_in[1];
    const float* bg = (const float*)d_in[2];
    const float* W1 = (const float*)d_in[3];
    const float* b1 = (const float*)d_in[4];
    const float* W2 = (const float*)d_in[5];
    const float* b2 = (const float*)d_in[6];
    float* out = (float*)d_out;

    cudaFuncSetAttribute(hgemm<DIM, HID, true, true>,
                         cudaFuncAttributeMaxDynamicSharedMemorySize, SMEM_BYTES);
    cudaFuncSetAttribute(hgemm<HID, DIM, false, false>,
                         cudaFuncAttributeMaxDynamicSharedMemorySize, SMEM_BYTES);

    __half* xh;  cudaGetSymbolAddress((void**)&xh,  g_xh);
    __half* w1h; cudaGetSymbolAddress((void**)&w1h, g_w1h);
    __half* w2h; cudaGetSymbolAddress((void**)&w2h, g_w2h);

    cvt_kernel<<<2048, 256>>>(x,  xh,  N_TOK * DIM / 4);
    cvt_kernel<<<2048, 256>>>(W1, w1h, NEXP * DIM * HID / 4);
    cvt_kernel<<<2048, 256>>>(W2, w2h, NEXP * HID * DIM / 4);

    gate_kernel<<<N_TOK / 8, 256>>>(x, Wg, bg);
    count_kernel<<<1, 256>>>();
    scatter_kernel<<<NK / 256, 256>>>();

    __half* hh; cudaGetSymbolAddress((void**)&hh, g_h);
    // GEMM1: h = gelu(x_gathered @ W1[e] + b1[e])   [32768, 2048] fp16
    hgemm<DIM, HID, true, true>
        <<<dim3(NK / BM, HID / BN, NEXP), 512, SMEM_BYTES>>>(xh, w1h, b1);
    // GEMM2: y = h @ W2[e] + b2[e]                  [32768, 1024] fp32
    hgemm<HID, DIM, false, false>
        <<<dim3(NK / BM, DIM / BN, NEXP), 512, SMEM_BYTES>>>(hh, w2h, b2);

    combine_kernel<<<N_TOK, 256>>>(x, out);
}

// round 4
// speedup vs baseline: 3.2528x; 1.0505x over previous
#include <cuda_runtime.h>
#include <cuda_fp16.h>
#include <math.h>
#include <stdint.h>

#define N_TOK 16384
#define DIM   1024
#define NEXP  8
#define HID   2048
#define NK    (N_TOK * 2)

// ---------------- scratch (no allocations allowed) -----------------------------
__device__ int    g_top_idx[NK];
__device__ float  g_top_w[NK];
__device__ int    g_off[NEXP + 1];
__device__ int    g_cursor[NEXP];
__device__ int    g_tok[NK];
__device__ int    g_pos[NK];
__device__ __half g_xh[(size_t)N_TOK * DIM];       // 32 MB  x fp16
__device__ __half g_w1h[(size_t)NEXP * DIM * HID]; // 32 MB  W1 fp16
__device__ __half g_w2h[(size_t)NEXP * HID * DIM]; // 32 MB  W2 fp16
__device__ __half g_h[(size_t)NK * HID];           // 134 MB gelu(xW1+b1) fp16
__device__ __half g_y[(size_t)NK * DIM];           // 67 MB  hW2+b2 fp16

// ---------------- PTX helpers --------------------------------------------------
__device__ __forceinline__ uint32_t smem_u32(const void* p) {
    uint32_t a;
    asm("{ .reg .u64 t; cvta.to.shared.u64 t, %1; cvt.u32.u64 %0, t; }" : "=r"(a) : "l"(p));
    return a;
}
__device__ __forceinline__ void cp16(uint32_t d, const void* s) {
    asm volatile("cp.async.cg.shared.global [%0], [%1], 16;" :: "r"(d), "l"(s));
}
#define CP_COMMIT() asm volatile("cp.async.commit_group;" ::: "memory")
#define CP_WAIT2()  asm volatile("cp.async.wait_group 2;" ::: "memory")

__device__ __forceinline__ void ldsm4(uint32_t* r, uint32_t a) {
    asm volatile("ldmatrix.sync.aligned.m8n8.x4.shared.b16 {%0,%1,%2,%3}, [%4];"
                 : "=r"(r[0]), "=r"(r[1]), "=r"(r[2]), "=r"(r[3]) : "r"(a));
}
__device__ __forceinline__ void ldsm4t(uint32_t* r, uint32_t a) {
    asm volatile("ldmatrix.sync.aligned.m8n8.x4.trans.shared.b16 {%0,%1,%2,%3}, [%4];"
                 : "=r"(r[0]), "=r"(r[1]), "=r"(r[2]), "=r"(r[3]) : "r"(a));
}
__device__ __forceinline__ void mma16816(float* c, const uint32_t* a, const uint32_t* b) {
    asm volatile("mma.sync.aligned.m16n8k16.row.col.f32.f16.f16.f32 "
                 "{%0,%1,%2,%3}, {%4,%5,%6,%7}, {%8,%9}, {%0,%1,%2,%3};"
                 : "+f"(c[0]), "+f"(c[1]), "+f"(c[2]), "+f"(c[3])
                 : "r"(a[0]), "r"(a[1]), "r"(a[2]), "r"(a[3]), "r"(b[0]), "r"(b[1]));
}
__device__ __forceinline__ float gelu_exact(float v) {
    return 0.5f * v * (1.0f + erff(v * 0.70710678118654752f));
}

// ---------------- fp32 -> fp16 convert (weights) -------------------------------
__global__ void cvt_kernel(const float* __restrict__ s, __half* __restrict__ d, int n4) {
    int i = blockIdx.x * blockDim.x + threadIdx.x;
    int stride = gridDim.x * blockDim.x;
    for (; i < n4; i += stride) {
        float4 v = ((const float4*)s)[i];
        __half2 h0 = __floats2half2_rn(v.x, v.y);
        __half2 h1 = __floats2half2_rn(v.z, v.w);
        ((uint2*)d)[i] = make_uint2(*(uint32_t*)&h0, *(uint32_t*)&h1);
    }
}

// ---------------- fused x-convert + gating -------------------------------------
// 8 warps/block, 1 token/warp. Wg transposed to smem [8][1024] for float4 reads.
__global__ void gatecvt_kernel(const float* __restrict__ x,
                               const float* __restrict__ Wg,
                               const float* __restrict__ bg) {
    __shared__ float sWg[NEXP][DIM];
    int tid = threadIdx.x, wid = tid >> 5, lane = tid & 31;
    // load Wg [D, E] transposed -> sWg[e][d]
    for (int i = tid; i < DIM * NEXP / 4; i += 256) {
        int d = i >> 1, half4 = i & 1;            // 2 float4 per Wg row
        float4 v = ((const float4*)(Wg + (size_t)d * NEXP))[half4];
        sWg[half4 * 4 + 0][d] = v.x; sWg[half4 * 4 + 1][d] = v.y;
        sWg[half4 * 4 + 2][d] = v.z; sWg[half4 * 4 + 3][d] = v.w;
    }
    __syncthreads();

    int tok = blockIdx.x * 8 + wid;
    const float* xr = x + (size_t)tok * DIM;
    __half* xo = g_xh + (size_t)tok * DIM;
    float acc[NEXP];
#pragma unroll
    for (int e = 0; e < NEXP; e++) acc[e] = 0.f;
#pragma unroll
    for (int it = 0; it < 8; it++) {
        int d = it * 128 + lane * 4;
        float4 xv = *(const float4*)(xr + d);
        __half2 h0 = __floats2half2_rn(xv.x, xv.y);
        __half2 h1 = __floats2half2_rn(xv.z, xv.w);
        *(uint2*)(xo + d) = make_uint2(*(uint32_t*)&h0, *(uint32_t*)&h1);
#pragma unroll
        for (int e = 0; e < NEXP; e++) {
            float4 wv = *(const float4*)&sWg[e][d];
            acc[e] += xv.x * wv.x + xv.y * wv.y + xv.z * wv.z + xv.w * wv.w;
        }
    }
#pragma unroll
    for (int e = 0; e < NEXP; e++)
#pragma unroll
        for (int s = 16; s > 0; s >>= 1)
            acc[e] += __shfl_xor_sync(0xffffffffu, acc[e], s);
    if (lane == 0) {
        float l[NEXP];
#pragma unroll
        for (int e = 0; e < NEXP; e++) l[e] = acc[e] + bg[e];
        int i0 = 0;
#pragma unroll
        for (int e = 1; e < NEXP; e++) if (l[e] > l[i0]) i0 = e;
        int i1 = (i0 == 0) ? 1 : 0;
#pragma unroll
        for (int e = 0; e < NEXP; e++) {
            if (e == i0) continue;
            if (l[e] > l[i1]) i1 = e;
        }
        float w0 = 1.f / (1.f + expf(l[i1] - l[i0]));
        g_top_idx[2 * tok]     = i0;
        g_top_idx[2 * tok + 1] = i1;
        g_top_w[2 * tok]       = w0;
        g_top_w[2 * tok + 1]   = 1.f - w0;
    }
}

__global__ void count_kernel() {
    __shared__ int cnt[NEXP];
    int tid = threadIdx.x;
    if (tid < NEXP) cnt[tid] = 0;
    __syncthreads();
    for (int i = tid; i < NK; i += blockDim.x)
        atomicAdd(&cnt[g_top_idx[i]], 1);
    __syncthreads();
    if (tid == 0) {
        int run = 0;
        for (int e = 0; e < NEXP; e++) { g_off[e] = run; g_cursor[e] = run; run += cnt[e]; }
        g_off[NEXP] = run;
    }
}

__global__ void scatter_kernel() {
    int i = blockIdx.x * blockDim.x + threadIdx.x;
    if (i >= NK) return;
    int e = g_top_idx[i];
    int p = atomicAdd(&g_cursor[e], 1);
    g_tok[p] = i >> 1;
    g_pos[i] = p;
}

// ---------------- fp16 expert GEMM ---------------------------------------------
// BM=128, BN=128, BK=32, 256 threads (8 warps 4x2, warp 32x64), 4 stages,
// 2 CTAs/SM (76.8 KB smem, <=128 regs). N-tile fastest in grid for L2 A-reuse.
#define BM 128
#define BN 128
#define BK 32
#define NST 4
#define A_PITCH 80
#define B_PITCH 272
#define STG_A   (BM * A_PITCH)               // 10240
#define STG_B   (BK * B_PITCH)               // 8704
#define STG_SZ  (STG_A + STG_B)              // 18944
#define OFF_BIAS (STG_SZ * NST)              // 75776
#define OFF_SRC  (OFF_BIAS + BN * 4)         // 76288
#define SMEM_BYTES (OFF_SRC + BM * 4)        // 76800
#define EP_PITCH 272

template <int KDIM, int NCOLS, bool GATHER, bool DOGELU>
__global__ __launch_bounds__(256, 2) void hgemm(
    const __half* __restrict__ Abase, const __half* __restrict__ Bbase,
    const float* __restrict__ biasbase, __half* __restrict__ Cout) {
    extern __shared__ __align__(128) char smem[];
    const int e     = blockIdx.z;
    const int moff  = g_off[e];
    const int M     = g_off[e + 1] - moff;
    const int rows0 = blockIdx.y * BM;       // M tile (slow index)
    if (rows0 >= M) return;
    const int n0 = blockIdx.x * BN;          // N tile (fast index -> A L2 reuse)

    const __half* Bexp = Bbase + (size_t)e * KDIM * NCOLS;
    const uint32_t sb = smem_u32(smem);
    const int tid  = threadIdx.x;
    const int wid  = tid >> 5, lane = tid & 31;
    const int wm = wid >> 1, wn = wid & 1;   // 4x2 warps, warp 32(m) x 64(n)
    const int g = lane >> 2, t = lane & 3;

    int*   sSrc  = (int*)(smem + OFF_SRC);
    float* sBias = (float*)(smem + OFF_BIAS);
    if (tid < BM) {
        int s = rows0 + tid; if (s >= M) s = M - 1;
        sSrc[tid] = GATHER ? g_tok[moff + s] : (moff + s);
    }
    if (tid < BN / 4)
        ((float4*)sBias)[tid] = ((const float4*)(biasbase + (size_t)e * NCOLS + n0))[tid];
    __syncthreads();

    // fill constants: A 2 chunks/thread, B 2 chunks/thread
    const __half* aRow[2];
    uint32_t aDst[2];
#pragma unroll
    for (int i = 0; i < 2; i++) {
        int idx = tid + i * 256;
        int r = idx >> 2, c = idx & 3;
        aRow[i] = Abase + (size_t)sSrc[r] * KDIM + c * 8;
        aDst[i] = (uint32_t)(r * A_PITCH + c * 16);
    }
    const int kb0 = tid >> 4, nc0 = tid & 15;
    const __half* bRow0 = Bexp + (size_t)kb0 * NCOLS + n0 + nc0 * 8;
    const __half* bRow1 = Bexp + (size_t)(kb0 + 16) * NCOLS + n0 + nc0 * 8;
    const uint32_t bDst0 = (uint32_t)(STG_A + kb0 * B_PITCH + nc0 * 16);
    const uint32_t bDst1 = bDst0 + 16 * B_PITCH;

    auto fill = [&](int kc) {
        int s = kc & (NST - 1);
        uint32_t base = sb + s * STG_SZ;
        cp16(base + aDst[0], aRow[0] + kc * BK);
        cp16(base + aDst[1], aRow[1] + kc * BK);
        cp16(base + bDst0, bRow0 + (size_t)kc * BK * NCOLS);
        cp16(base + bDst1, bRow1 + (size_t)kc * BK * NCOLS);
    };

    // LDSM lane addresses
    const int lr = lane & 15, ls = lane >> 4;
    uint32_t aAddr[2], bAddr[2][4];
#pragma unroll
    for (int mi = 0; mi < 2; mi++)
        aAddr[mi] = (uint32_t)((wm * 32 + mi * 16 + lr) * A_PITCH + ls * 16);
#pragma unroll
    for (int kk = 0; kk < 2; kk++)
#pragma unroll
        for (int p = 0; p < 4; p++)
            bAddr[kk][p] = (uint32_t)(STG_A + (kk * 16 + lr) * B_PITCH +
                                      (wn * 8 + p * 2 + ls) * 16);

    float acc[2][8][4];
#pragma unroll
    for (int mi = 0; mi < 2; mi++)
#pragma unroll
        for (int ni = 0; ni < 8; ni++)
#pragma unroll
            for (int q = 0; q < 4; q++) acc[mi][ni][q] = 0.f;

    const int NC = KDIM / BK;
    fill(0); CP_COMMIT();
    fill(1); CP_COMMIT();
    fill(2); CP_COMMIT();

    for (int kc = 0; kc < NC; kc++) {
        int s = kc & (NST - 1);
        uint32_t base = sb + s * STG_SZ;
        CP_WAIT2();
        __syncthreads();
#pragma unroll
        for (int kk = 0; kk < 2; kk++) {
            uint32_t af[2][4], bf[8][2];
#pragma unroll
            for (int mi = 0; mi < 2; mi++)
                ldsm4(af[mi], base + aAddr[mi] + kk * 32);
#pragma unroll
            for (int p = 0; p < 4; p++) {
                uint32_t r4[4];
                ldsm4t(r4, base + bAddr[kk][p]);
                bf[2 * p][0] = r4[0]; bf[2 * p][1] = r4[1];
                bf[2 * p + 1][0] = r4[2]; bf[2 * p + 1][1] = r4[3];
            }
#pragma unroll
            for (int mi = 0; mi < 2; mi++)
#pragma unroll
                for (int ni = 0; ni < 8; ni++)
                    mma16816(acc[mi][ni], af[mi], bf[ni]);
        }
        if (kc + 3 < NC) fill(kc + 3);
        CP_COMMIT();
    }
    __syncthreads();

    // unified epilogue: bias (+gelu) -> fp16, stage through smem, STG.128
    char* ep = smem;
#pragma unroll
    for (int mi = 0; mi < 2; mi++)
#pragma unroll
        for (int ni = 0; ni < 8; ni++) {
            int col = wn * 64 + ni * 8 + 2 * t;
            float bv0 = sBias[col], bv1 = sBias[col + 1];
            int rlo = wm * 32 + mi * 16 + g;
            float v0 = acc[mi][ni][0] + bv0;
            float v1 = acc[mi][ni][1] + bv1;
            float v2 = acc[mi][ni][2] + bv0;
            float v3 = acc[mi][ni][3] + bv1;
            if (DOGELU) {
                v0 = gelu_exact(v0); v1 = gelu_exact(v1);
                v2 = gelu_exact(v2); v3 = gelu_exact(v3);
            }
            __half2 hlo = __floats2half2_rn(v0, v1);
            __half2 hhi = __floats2half2_rn(v2, v3);
            *(__half2*)(ep + rlo * EP_PITCH + col * 2) = hlo;
            *(__half2*)(ep + (rlo + 8) * EP_PITCH + col * 2) = hhi;
        }
    __syncthreads();
#pragma unroll
    for (int it = 0; it < 8; it++) {
        int id = it * 256 + tid;
        int r = id >> 4, c = id & 15;
        if (rows0 + r < M) {
            uint4 v = *(uint4*)(ep + r * EP_PITCH + c * 16);
            *(uint4*)(Cout + (size_t)(moff + rows0 + r) * NCOLS + n0 + c * 8) = v;
        }
    }
}

// ---------------- combine (fp16 y) ---------------------------------------------
__global__ void combine_kernel(const float* __restrict__ x, float* __restrict__ out) {
    int idx = blockIdx.x * blockDim.x + threadIdx.x;   // over N * (D/8)
    int n = idx >> 7;
    int c = (idx & 127) * 8;
    int p0 = g_pos[2 * n], p1 = g_pos[2 * n + 1];
    float w0 = g_top_w[2 * n], w1 = g_top_w[2 * n + 1];
    const float* xr = x + (size_t)n * DIM + c;
    float4 x0 = ((const float4*)xr)[0];
    float4 x1 = ((const float4*)xr)[1];
    uint4 ya = *(const uint4*)(g_y + (size_t)p0 * DIM + c);
    uint4 yb = *(const uint4*)(g_y + (size_t)p1 * DIM + c);
    float2 a0 = __half22float2(*(__half2*)&ya.x), a1 = __half22float2(*(__half2*)&ya.y);
    float2 a2 = __half22float2(*(__half2*)&ya.z), a3 = __half22float2(*(__half2*)&ya.w);
    float2 b0 = __half22float2(*(__half2*)&yb.x), b1 = __half22float2(*(__half2*)&yb.y);
    float2 b2 = __half22float2(*(__half2*)&yb.z), b3 = __half22float2(*(__half2*)&yb.w);
    float4 o0, o1;
    o0.x = x0.x + w0 * a0.x + w1 * b0.x;
    o0.y = x0.y + w0 * a0.y + w1 * b0.y;
    o0.z = x0.z + w0 * a1.x + w1 * b1.x;
    o0.w = x0.w + w0 * a1.y + w1 * b1.y;
    o1.x = x1.x + w0 * a2.x + w1 * b2.x;
    o1.y = x1.y + w0 * a2.y + w1 * b2.y;
    o1.z = x1.z + w0 * a3.x + w1 * b3.x;
    o1.w = x1.w + w0 * a3.y + w1 * b3.y;
    float* orow = out + (size_t)n * DIM + c;
    ((float4*)orow)[0] = o0;
    ((float4*)orow)[1] = o1;
}

// ---------------- launch -------------------------------------------------------
extern "C" void kernel_launch(void* const* d_in, const int* in_sizes, int n_in,
                              void* d_out, int out_size) {
    const float* x  = (const float*)d_in[0];
    const float* Wg = (const float*)d_in[1];
    const float* bg = (const float*)d_in[2];
    const float* W1 = (const float*)d_in[3];
    const float* b1 = (const float*)d_in[4];
    const float* W2 = (const float*)d_in[5];
    const float* b2 = (const float*)d_in[6];
    float* out = (float*)d_out;

    cudaFuncSetAttribute(hgemm<DIM, HID, true, true>,
                         cudaFuncAttributeMaxDynamicSharedMemorySize, SMEM_BYTES);
    cudaFuncSetAttribute(hgemm<HID, DIM, false, false>,
                         cudaFuncAttributeMaxDynamicSharedMemorySize, SMEM_BYTES);

    __half *xh, *w1h, *w2h, *hh, *yh;
    cudaGetSymbolAddress((void**)&xh,  g_xh);
    cudaGetSymbolAddress((void**)&w1h, g_w1h);
    cudaGetSymbolAddress((void**)&w2h, g_w2h);
    cudaGetSymbolAddress((void**)&hh,  g_h);
    cudaGetSymbolAddress((void**)&yh,  g_y);

    cvt_kernel<<<2048, 256>>>(W1, w1h, NEXP * DIM * HID / 4);
    cvt_kernel<<<2048, 256>>>(W2, w2h, NEXP * HID * DIM / 4);
    gatecvt_kernel<<<N_TOK / 8, 256>>>(x, Wg, bg);
    count_kernel<<<1, 256>>>();
    scatter_kernel<<<NK / 256, 256>>>();

    // GEMM1: h = gelu(x_gathered @ W1[e] + b1[e])   [32768, 2048] fp16
    hgemm<DIM, HID, true, true>
        <<<dim3(HID / BN, NK / BM, NEXP), 256, SMEM_BYTES>>>(xh, w1h, b1, hh);
    // GEMM2: y = h @ W2[e] + b2[e]                  [32768, 1024] fp16
    hgemm<HID, DIM, false, false>
        <<<dim3(DIM / BN, NK / BM, NEXP), 256, SMEM_BYTES>>>(hh, w2h, b2, yh);

    combine_kernel<<<N_TOK * 128 / 256, 256>>>(x, out);
}

// round 5
// speedup vs baseline: 3.3417x; 1.0273x over previous
#include <cuda_runtime.h>
#include <cuda_fp16.h>
#include <math.h>
#include <stdint.h>

#define N_TOK 16384
#define DIM   1024
#define NEXP  8
#define HID   2048
#define NK    (N_TOK * 2)
#define NPERS 304          // persistent CTAs: 152 SMs x 2

// ---------------- scratch (no allocations allowed) -----------------------------
__device__ int    g_top_idx[NK];
__device__ float  g_top_w[NK];
__device__ int    g_cnt[NEXP];            // per-expert counts (reset by combine)
__device__ int    g_cnt2[NEXP];           // scatter cursors   (reset by combine)
__device__ int    g_off[NEXP + 1];
__device__ int    g_tile_off[NEXP + 1];   // per-expert M-tile prefix
__device__ int    g_wq[2];                // GEMM work queues  (reset by combine)
__device__ int    g_tok[NK];
__device__ int    g_pos[NK];
__device__ __half g_xh[(size_t)N_TOK * DIM];
__device__ __half g_w1h[(size_t)NEXP * DIM * HID];
__device__ __half g_w2h[(size_t)NEXP * HID * DIM];
__device__ __half g_h[(size_t)NK * HID];
__device__ __half g_y[(size_t)NK * DIM];

// ---------------- PTX helpers --------------------------------------------------
__device__ __forceinline__ uint32_t smem_u32(const void* p) {
    uint32_t a;
    asm("{ .reg .u64 t; cvta.to.shared.u64 t, %1; cvt.u32.u64 %0, t; }" : "=r"(a) : "l"(p));
    return a;
}
__device__ __forceinline__ void cp16(uint32_t d, const void* s) {
    asm volatile("cp.async.cg.shared.global [%0], [%1], 16;" :: "r"(d), "l"(s));
}
#define CP_COMMIT() asm volatile("cp.async.commit_group;" ::: "memory")
#define CP_WAIT2()  asm volatile("cp.async.wait_group 2;" ::: "memory")

__device__ __forceinline__ void ldsm4(uint32_t* r, uint32_t a) {
    asm volatile("ldmatrix.sync.aligned.m8n8.x4.shared.b16 {%0,%1,%2,%3}, [%4];"
                 : "=r"(r[0]), "=r"(r[1]), "=r"(r[2]), "=r"(r[3]) : "r"(a));
}
__device__ __forceinline__ void ldsm4t(uint32_t* r, uint32_t a) {
    asm volatile("ldmatrix.sync.aligned.m8n8.x4.trans.shared.b16 {%0,%1,%2,%3}, [%4];"
                 : "=r"(r[0]), "=r"(r[1]), "=r"(r[2]), "=r"(r[3]) : "r"(a));
}
__device__ __forceinline__ void mma16816(float* c, const uint32_t* a, const uint32_t* b) {
    asm volatile("mma.sync.aligned.m16n8k16.row.col.f32.f16.f16.f32 "
                 "{%0,%1,%2,%3}, {%4,%5,%6,%7}, {%8,%9}, {%0,%1,%2,%3};"
                 : "+f"(c[0]), "+f"(c[1]), "+f"(c[2]), "+f"(c[3])
                 : "r"(a[0]), "r"(a[1]), "r"(a[2]), "r"(a[3]), "r"(b[0]), "r"(b[1]));
}
__device__ __forceinline__ float gelu_exact(float v) {
    return 0.5f * v * (1.0f + erff(v * 0.70710678118654752f));
}

// ---------------- fp32 -> fp16 convert (weights) -------------------------------
__global__ void cvt_kernel(const float* __restrict__ s, __half* __restrict__ d, int n4) {
    int i = blockIdx.x * blockDim.x + threadIdx.x;
    int stride = gridDim.x * blockDim.x;
    for (; i < n4; i += stride) {
        float4 v = ((const float4*)s)[i];
        __half2 h0 = __floats2half2_rn(v.x, v.y);
        __half2 h1 = __floats2half2_rn(v.z, v.w);
        ((uint2*)d)[i] = make_uint2(*(uint32_t*)&h0, *(uint32_t*)&h1);
    }
}

// ---------------- fused x-convert + gating + expert counts ---------------------
__global__ void gatecvt_kernel(const float* __restrict__ x,
                               const float* __restrict__ Wg,
                               const float* __restrict__ bg) {
    __shared__ float sWg[NEXP][DIM];
    int tid = threadIdx.x, wid = tid >> 5, lane = tid & 31;
    for (int i = tid; i < DIM * NEXP / 4; i += 256) {
        int d = i >> 1, half4 = i & 1;
        float4 v = ((const float4*)(Wg + (size_t)d * NEXP))[half4];
        sWg[half4 * 4 + 0][d] = v.x; sWg[half4 * 4 + 1][d] = v.y;
        sWg[half4 * 4 + 2][d] = v.z; sWg[half4 * 4 + 3][d] = v.w;
    }
    __syncthreads();

    int tok = blockIdx.x * 8 + wid;
    const float* xr = x + (size_t)tok * DIM;
    __half* xo = g_xh + (size_t)tok * DIM;
    float acc[NEXP];
#pragma unroll
    for (int e = 0; e < NEXP; e++) acc[e] = 0.f;
#pragma unroll
    for (int it = 0; it < 8; it++) {
        int d = it * 128 + lane * 4;
        float4 xv = *(const float4*)(xr + d);
        __half2 h0 = __floats2half2_rn(xv.x, xv.y);
        __half2 h1 = __floats2half2_rn(xv.z, xv.w);
        *(uint2*)(xo + d) = make_uint2(*(uint32_t*)&h0, *(uint32_t*)&h1);
#pragma unroll
        for (int e = 0; e < NEXP; e++) {
            float4 wv = *(const float4*)&sWg[e][d];
            acc[e] += xv.x * wv.x + xv.y * wv.y + xv.z * wv.z + xv.w * wv.w;
        }
    }
#pragma unroll
    for (int e = 0; e < NEXP; e++)
#pragma unroll
        for (int s = 16; s > 0; s >>= 1)
            acc[e] += __shfl_xor_sync(0xffffffffu, acc[e], s);
    if (lane == 0) {
        float l[NEXP];
#pragma unroll
        for (int e = 0; e < NEXP; e++) l[e] = acc[e] + bg[e];
        int i0 = 0;
#pragma unroll
        for (int e = 1; e < NEXP; e++) if (l[e] > l[i0]) i0 = e;
        int i1 = (i0 == 0) ? 1 : 0;
#pragma unroll
        for (int e = 0; e < NEXP; e++) {
            if (e == i0) continue;
            if (l[e] > l[i1]) i1 = e;
        }
        float w0 = 1.f / (1.f + expf(l[i1] - l[i0]));
        g_top_idx[2 * tok]     = i0;
        g_top_idx[2 * tok + 1] = i1;
        g_top_w[2 * tok]       = w0;
        g_top_w[2 * tok + 1]   = 1.f - w0;
        atomicAdd(&g_cnt[i0], 1);
        atomicAdd(&g_cnt[i1], 1);
    }
}

// ---------------- routing: offsets + scatter + tile offsets --------------------
__global__ void route_kernel() {
    __shared__ int soff[NEXP];
    int tid = threadIdx.x;
    if (tid == 0) {
        int run = 0;
#pragma unroll
        for (int e = 0; e < NEXP; e++) { soff[e] = run; run += g_cnt[e]; }
    }
    __syncthreads();
    int i = blockIdx.x * blockDim.x + tid;
    if (i < NK) {
        int e = g_top_idx[i];
        int p = soff[e] + atomicAdd(&g_cnt2[e], 1);
        g_tok[p] = i >> 1;
        g_pos[i] = p;
    }
    if (blockIdx.x == 0 && tid == 0) {
        int run = 0, trun = 0;
#pragma unroll
        for (int e = 0; e < NEXP; e++) {
            g_off[e] = run; g_tile_off[e] = trun;
            trun += (g_cnt[e] + 127) >> 7;
            run += g_cnt[e];
        }
        g_off[NEXP] = run; g_tile_off[NEXP] = trun;
    }
}

// ---------------- persistent fp16 expert GEMM ----------------------------------
// BM=128, BN=128, BK=32, 256 threads (8 warps 4x2, warp 32x64), 4 stages,
// 2 CTAs/SM. Work queue over (global M-tile, N-tile).
#define BM 128
#define BN 128
#define BK 32
#define NST 4
#define A_PITCH 80
#define B_PITCH 272
#define STG_A   (BM * A_PITCH)
#define STG_B   (BK * B_PITCH)
#define STG_SZ  (STG_A + STG_B)              // 18944
#define OFF_BIAS (STG_SZ * NST)              // 75776
#define OFF_SRC  (OFF_BIAS + BN * 4)         // 76288
#define SMEM_BYTES (OFF_SRC + BM * 4)        // 76800
#define EP_PITCH 272

template <int KDIM, int NCOLS, bool GATHER, bool DOGELU, int QID>
__global__ __launch_bounds__(256, 2) void hgemm(
    const __half* __restrict__ Abase, const __half* __restrict__ Bbase,
    const float* __restrict__ biasbase, __half* __restrict__ Cout) {
    extern __shared__ __align__(128) char smem[];
    __shared__ int sW;
    __shared__ int sTOF[NEXP + 1];
    const uint32_t sb = smem_u32(smem);
    const int tid  = threadIdx.x;
    const int wid  = tid >> 5, lane = tid & 31;
    const int wm = wid >> 1, wn = wid & 1;
    const int g = lane >> 2, t = lane & 3;
    const int NT = NCOLS / BN;

    if (tid <= NEXP) sTOF[tid] = g_tile_off[tid];

    int*   sSrc  = (int*)(smem + OFF_SRC);
    float* sBias = (float*)(smem + OFF_BIAS);

    // LDSM lane addresses (tile-invariant)
    const int lr = lane & 15, ls = lane >> 4;
    uint32_t aAddr[2], bAddr[2][4];
#pragma unroll
    for (int mi = 0; mi < 2; mi++)
        aAddr[mi] = (uint32_t)((wm * 32 + mi * 16 + lr) * A_PITCH + ls * 16);
#pragma unroll
    for (int kk = 0; kk < 2; kk++)
#pragma unroll
        for (int p = 0; p < 4; p++)
            bAddr[kk][p] = (uint32_t)(STG_A + (kk * 16 + lr) * B_PITCH +
                                      (wn * 8 + p * 2 + ls) * 16);

    while (true) {
        if (tid == 0) sW = atomicAdd(&g_wq[QID], 1);
        __syncthreads();
        const int w = sW;
        if (w >= sTOF[NEXP] * NT) break;
        const int gm = w / NT, nt = w % NT;
        int e = 0;
#pragma unroll
        for (int k = 1; k < NEXP; k++) if (gm >= sTOF[k]) e = k;
        const int moff  = g_off[e];
        const int M     = g_off[e + 1] - moff;
        const int rows0 = (gm - sTOF[e]) * BM;
        const int n0    = nt * BN;
        const __half* Bexp = Bbase + (size_t)e * KDIM * NCOLS;

        if (tid < BM) {
            int s = rows0 + tid; if (s >= M) s = M - 1;
            sSrc[tid] = GATHER ? g_tok[moff + s] : (moff + s);
        }
        if (tid < BN / 4)
            ((float4*)sBias)[tid] =
                ((const float4*)(biasbase + (size_t)e * NCOLS + n0))[tid];
        __syncthreads();

        // fill constants for this tile
        const __half* aRow[2];
        uint32_t aDst[2];
#pragma unroll
        for (int i = 0; i < 2; i++) {
            int idx = tid + i * 256;
            int r = idx >> 2, c = idx & 3;
            aRow[i] = Abase + (size_t)sSrc[r] * KDIM + c * 8;
            aDst[i] = (uint32_t)(r * A_PITCH + c * 16);
        }
        const int kb0 = tid >> 4, nc0 = tid & 15;
        const __half* bRow0 = Bexp + (size_t)kb0 * NCOLS + n0 + nc0 * 8;
        const __half* bRow1 = Bexp + (size_t)(kb0 + 16) * NCOLS + n0 + nc0 * 8;
        const uint32_t bDst0 = (uint32_t)(STG_A + kb0 * B_PITCH + nc0 * 16);
        const uint32_t bDst1 = bDst0 + 16 * B_PITCH;

        auto fill = [&](int kc) {
            int s = kc & (NST - 1);
            uint32_t base = sb + s * STG_SZ;
            cp16(base + aDst[0], aRow[0] + kc * BK);
            cp16(base + aDst[1], aRow[1] + kc * BK);
            cp16(base + bDst0, bRow0 + (size_t)kc * BK * NCOLS);
            cp16(base + bDst1, bRow1 + (size_t)kc * BK * NCOLS);
        };

        float acc[2][8][4];
#pragma unroll
        for (int mi = 0; mi < 2; mi++)
#pragma unroll
            for (int ni = 0; ni < 8; ni++)
#pragma unroll
                for (int q = 0; q < 4; q++) acc[mi][ni][q] = 0.f;

        const int NC = KDIM / BK;
        fill(0); CP_COMMIT();
        fill(1); CP_COMMIT();
        fill(2); CP_COMMIT();

        for (int kc = 0; kc < NC; kc++) {
            int s = kc & (NST - 1);
            uint32_t base = sb + s * STG_SZ;
            CP_WAIT2();
            __syncthreads();
#pragma unroll
            for (int kk = 0; kk < 2; kk++) {
                uint32_t af[2][4], bf[8][2];
#pragma unroll
                for (int mi = 0; mi < 2; mi++)
                    ldsm4(af[mi], base + aAddr[mi] + kk * 32);
#pragma unroll
                for (int p = 0; p < 4; p++) {
                    uint32_t r4[4];
                    ldsm4t(r4, base + bAddr[kk][p]);
                    bf[2 * p][0] = r4[0]; bf[2 * p][1] = r4[1];
                    bf[2 * p + 1][0] = r4[2]; bf[2 * p + 1][1] = r4[3];
                }
#pragma unroll
                for (int mi = 0; mi < 2; mi++)
#pragma unroll
                    for (int ni = 0; ni < 8; ni++)
                        mma16816(acc[mi][ni], af[mi], bf[ni]);
            }
            if (kc + 3 < NC) fill(kc + 3);
            CP_COMMIT();
        }
        __syncthreads();

        // epilogue: bias(+gelu) -> fp16 via smem stage, STG.128
        char* ep = smem;
#pragma unroll
        for (int mi = 0; mi < 2; mi++)
#pragma unroll
            for (int ni = 0; ni < 8; ni++) {
                int col = wn * 64 + ni * 8 + 2 * t;
                float bv0 = sBias[col], bv1 = sBias[col + 1];
                int rlo = wm * 32 + mi * 16 + g;
                float v0 = acc[mi][ni][0] + bv0;
                float v1 = acc[mi][ni][1] + bv1;
                float v2 = acc[mi][ni][2] + bv0;
                float v3 = acc[mi][ni][3] + bv1;
                if (DOGELU) {
                    v0 = gelu_exact(v0); v1 = gelu_exact(v1);
                    v2 = gelu_exact(v2); v3 = gelu_exact(v3);
                }
                __half2 hlo = __floats2half2_rn(v0, v1);
                __half2 hhi = __floats2half2_rn(v2, v3);
                *(__half2*)(ep + rlo * EP_PITCH + col * 2) = hlo;
                *(__half2*)(ep + (rlo + 8) * EP_PITCH + col * 2) = hhi;
            }
        __syncthreads();
#pragma unroll
        for (int it = 0; it < 8; it++) {
            int id = it * 256 + tid;
            int r = id >> 4, c = id & 15;
            if (rows0 + r < M) {
                uint4 v = *(uint4*)(ep + r * EP_PITCH + c * 16);
                *(uint4*)(Cout + (size_t)(moff + rows0 + r) * NCOLS + n0 + c * 8) = v;
            }
        }
        // loop-top __syncthreads protects ep smem before next tile's writes
    }
}

// ---------------- combine (fp16 y) + state reset for graph replay --------------
__global__ void combine_kernel(const float* __restrict__ x, float* __restrict__ out) {
    int idx = blockIdx.x * blockDim.x + threadIdx.x;
    int n = idx >> 7;
    int c = (idx & 127) * 8;
    int p0 = g_pos[2 * n], p1 = g_pos[2 * n + 1];
    float w0 = g_top_w[2 * n], w1 = g_top_w[2 * n + 1];
    const float* xr = x + (size_t)n * DIM + c;
    float4 x0 = ((const float4*)xr)[0];
    float4 x1 = ((const float4*)xr)[1];
    uint4 ya = *(const uint4*)(g_y + (size_t)p0 * DIM + c);
    uint4 yb = *(const uint4*)(g_y + (size_t)p1 * DIM + c);
    float2 a0 = __half22float2(*(__half2*)&ya.x), a1 = __half22float2(*(__half2*)&ya.y);
    float2 a2 = __half22float2(*(__half2*)&ya.z), a3 = __half22float2(*(__half2*)&ya.w);
    float2 b0 = __half22float2(*(__half2*)&yb.x), b1 = __half22float2(*(__half2*)&yb.y);
    float2 b2 = __half22float2(*(__half2*)&yb.z), b3 = __half22float2(*(__half2*)&yb.w);
    float4 o0, o1;
    o0.x = x0.x + w0 * a0.x + w1 * b0.x;
    o0.y = x0.y + w0 * a0.y + w1 * b0.y;
    o0.z = x0.z + w0 * a1.x + w1 * b1.x;
    o0.w = x0.w + w0 * a1.y + w1 * b1.y;
    o1.x = x1.x + w0 * a2.x + w1 * b2.x;
    o1.y = x1.y + w0 * a2.y + w1 * b2.y;
    o1.z = x1.z + w0 * a3.x + w1 * b3.x;
    o1.w = x1.w + w0 * a3.y + w1 * b3.y;
    float* orow = out + (size_t)n * DIM + c;
    ((float4*)orow)[0] = o0;
    ((float4*)orow)[1] = o1;
    // reset routing/work state so every graph replay starts from zeroed globals
    if (blockIdx.x == 0 && threadIdx.x < NEXP) {
        g_cnt[threadIdx.x] = 0;
        g_cnt2[threadIdx.x] = 0;
        if (threadIdx.x < 2) g_wq[threadIdx.x] = 0;
    }
}

// ---------------- launch -------------------------------------------------------
extern "C" void kernel_launch(void* const* d_in, const int* in_sizes, int n_in,
                              void* d_out, int out_size) {
    const float* x  = (const float*)d_in[0];
    const float* Wg = (const float*)d_in[1];
    const float* bg = (const float*)d_in[2];
    const float* W1 = (const float*)d_in[3];
    const float* b1 = (const float*)d_in[4];
    const float* W2 = (const float*)d_in[5];
    const float* b2 = (const float*)d_in[6];
    float* out = (float*)d_out;

    cudaFuncSetAttribute(hgemm<DIM, HID, true, true, 0>,
                         cudaFuncAttributeMaxDynamicSharedMemorySize, SMEM_BYTES);
    cudaFuncSetAttribute(hgemm<HID, DIM, false, false, 1>,
                         cudaFuncAttributeMaxDynamicSharedMemorySize, SMEM_BYTES);

    __half *xh, *w1h, *w2h, *hh, *yh;
    cudaGetSymbolAddress((void**)&xh,  g_xh);
    cudaGetSymbolAddress((void**)&w1h, g_w1h);
    cudaGetSymbolAddress((void**)&w2h, g_w2h);
    cudaGetSymbolAddress((void**)&hh,  g_h);
    cudaGetSymbolAddress((void**)&yh,  g_y);

    gatecvt_kernel<<<N_TOK / 8, 256>>>(x, Wg, bg);             // 0
    route_kernel<<<NK / 256, 256>>>();                          // 1
    cvt_kernel<<<2048, 256>>>(W1, w1h, NEXP * DIM * HID / 4);   // 2
    hgemm<DIM, HID, true, true, 0>                              // 3 (profiled)
        <<<NPERS, 256, SMEM_BYTES>>>(xh, w1h, b1, hh);
    cvt_kernel<<<2048, 256>>>(W2, w2h, NEXP * HID * DIM / 4);   // 4
    hgemm<HID, DIM, false, false, 1>                            // 5
        <<<NPERS, 256, SMEM_BYTES>>>(hh, w2h, b2, yh);
    combine_kernel<<<N_TOK * 128 / 256, 256>>>(x, out);         // 6
}